// round 14
// baseline (speedup 1.0000x reference)
#include <cuda_runtime.h>
#include <cuda_fp16.h>
#include <cstdint>

// ---------------------------------------------------------------------------
// Seq2SeqForecast: 2-layer GRU encoder (B=512, T=336, H=512) + 48-step GRU
// decoder with scalar head.
//
// R13 vs R12 (6380us): inner-pipeline rebuild.
//  * manual software-pipelined ldmatrix->mma (prefetch next fragments while
//    issuing current mma pairs) — removes per-warp exposed LDSM latency.
//  * 4-stage cp.async ring at K=32 chunks, ONE __syncthreads per chunk,
//    wait<2> lookahead (~2 chunks of latency cover).
//  * stage layout [B|A] so PDL still prefetches weights pre-griddepcontrol.
// Kept: PDL chaining (R12, +235us), fused enc step, ldmatrix, epilogues.
// ---------------------------------------------------------------------------

#define HDIM   512
#define BATCH  512
#define TSTEPS 336
#define HORIZON 48
#define G3H    (3 * HDIM)          // 1536

// fp16 weight copies
__device__ __half g_Whh0[G3H * HDIM];
__device__ __half g_Wih1[G3H * HDIM];
__device__ __half g_Whh1[G3H * HDIM];
__device__ __half g_cWhh[G3H * HDIM];

// hidden-state ping-pong buffers (fp32 master + fp16 shadow for MMA)
__device__ float  g_h0_f32[2][BATCH * HDIM];
__device__ __half g_h0_f16[2][BATCH * HDIM];
__device__ float  g_h1_f32[2][BATCH * HDIM];
__device__ __half g_h1_f16[2][BATCH * HDIM];
__device__ float  g_hd_f32[2][BATCH * HDIM];
__device__ __half g_hd_f16[2][BATCH * HDIM];
__device__ float  g_lastv[BATCH];

// ---------------------------------------------------------------------------
// helpers
// ---------------------------------------------------------------------------
__device__ __forceinline__ void mma16816(float (&c)[4], const uint32_t (&a)[4],
                                         uint32_t b0, uint32_t b1) {
    asm volatile(
        "mma.sync.aligned.m16n8k16.row.col.f32.f16.f16.f32 "
        "{%0,%1,%2,%3}, {%4,%5,%6,%7}, {%8,%9}, {%0,%1,%2,%3};\n"
        : "+f"(c[0]), "+f"(c[1]), "+f"(c[2]), "+f"(c[3])
        : "r"(a[0]), "r"(a[1]), "r"(a[2]), "r"(a[3]), "r"(b0), "r"(b1));
}

__device__ __forceinline__ void ldsm4(uint32_t (&r)[4], uint32_t saddr) {
    asm volatile(
        "ldmatrix.sync.aligned.m8n8.x4.shared.b16 {%0,%1,%2,%3}, [%4];\n"
        : "=r"(r[0]), "=r"(r[1]), "=r"(r[2]), "=r"(r[3]) : "r"(saddr));
}

__device__ __forceinline__ float sigmoidf_(float x) {
    return 1.0f / (1.0f + expf(-x));
}

__device__ __forceinline__ void cp16(uint32_t dst, const void* src) {
    asm volatile("cp.async.cg.shared.global [%0], [%1], 16;\n"
                 :: "r"(dst), "l"(src));
}
__device__ __forceinline__ void cp_commit() {
    asm volatile("cp.async.commit_group;\n");
}
template <int N>
__device__ __forceinline__ void cp_wait() {
    asm volatile("cp.async.wait_group %0;\n" :: "n"(N));
}

// PDL: no-ops when the launch lacks the programmatic-serialization attribute.
__device__ __forceinline__ void pdl_wait() {
    asm volatile("griddepcontrol.wait;" ::: "memory");
}
__device__ __forceinline__ void pdl_trigger() {
    asm volatile("griddepcontrol.launch_dependents;" ::: "memory");
}

// ---------------------------------------------------------------------------
// Core GRU tile: block computes a 64(batch) x 32(hidden) tile of h_new.
// gh = h_prev @ Wghᵀ (+bhh) via MMA; gi via MMA (HAS_GI) or small dot.
//
// Pipeline: K split into 16 chunks of 32; 4-stage cp.async ring; stage rows
// (row stride 40 halves): B0[96] [B1[96]] A0[64] [A1[64]].
// One __syncthreads per chunk; wait<2> lookahead; manual ldsm/mma pipelining.
// All granule sources are module __device__ globals -> int32 offsets from
// g_Whh0 (register diet).
// ---------------------------------------------------------------------------
template <bool HAS_GI, int IN_FEAT, bool HAS_XFIRST>
__device__ __forceinline__ void gru_block(
    __half* __restrict__ smem, int m0, int n0,
    const __half* __restrict__ Agh, const __half* __restrict__ Wgh,
    const __half* __restrict__ Agi, const __half* __restrict__ Wgi,
    const float* __restrict__ bih, const float* __restrict__ bhh,
    const float* __restrict__ WihS,
    const float* __restrict__ xrow, int xstride,
    const float* __restrict__ xfirst,
    const float* __restrict__ hprev, float* __restrict__ hout,
    __half* __restrict__ hout16) {

    constexpr int SR  = HAS_GI ? 320 : 160;     // stage rows
    constexpr int SH  = SR * 40;                // stage halves
    constexpr int NG  = SR * 4;                 // 16B granules per chunk
    constexpr int NB  = HAS_GI ? 768 : 384;     // B-class granules
    constexpr int NPT = (NG + 255) / 256;       // granules per thread
    constexpr int ABASE = HAS_GI ? 192 : 96;    // A0 stage-row base

    const int tid  = threadIdx.x;
    const int lane = tid & 31;
    const int wid  = tid >> 5;       // 8 warps
    const int wm   = wid >> 1;       // 4 warps along M
    const int wn   = wid & 1;        // 2 warps along N
    const int g4   = lane >> 2;
    const int t4   = lane & 3;

    const uint32_t sbase = (uint32_t)__cvta_generic_to_shared(smem);
    const char* gbase = (const char*)g_Whh0;

    // ---- per-thread granule source offsets (int32 from gbase) ----
    int goff[NPT];
#pragma unroll
    for (int i = 0; i < NPT; i++) {
        int g = tid + i * 256;
        const char* s = gbase;
        if (g < NG) {
            int c4 = g & 3, r = g >> 2;
            if (g < NB) {
                int rr = (r >= 96) ? r - 96 : r;
                const __half* W = (r >= 96) ? Wgi : Wgh;
                int gate = rr >> 5, col = n0 + (rr & 31);
                s = (const char*)(W + (size_t)(gate * HDIM + col) * HDIM + c4 * 8);
            } else {
                bool a1 = HAS_GI && (r >= 256);
                int rr = r - (a1 ? 256 : ABASE);
                const __half* Ap = a1 ? Agi : Agh;
                s = (const char*)(Ap + (size_t)(m0 + rr) * HDIM + c4 * 8);
            }
        }
        goff[i] = (int)(s - gbase);
    }

    // mode: 0 = B granules only, 1 = A only, 2 = all
    auto stage = [&](int c, int mode) {
        const uint32_t so = sbase + (uint32_t)((c & 3) * SH * 2);
#pragma unroll
        for (int i = 0; i < NPT; i++) {
            int g = tid + i * 256;
            if (g < NG) {
                bool isb = g < NB;
                if (mode == 2 || (mode == 0 && isb) || (mode == 1 && !isb))
                    cp16(so + (uint32_t)((g >> 2) * 80 + (g & 3) * 16),
                         gbase + goff[i] + c * 64);
            }
        }
    };

    // ---- ldmatrix per-lane offsets ----
    const int lane15 = lane & 15;
    const int lhi8   = (lane >> 4) * 8;
    uint32_t boff[3];
#pragma unroll
    for (int g = 0; g < 3; g++)
        boff[g] = (uint32_t)(((g * 32 + wn * 16 + lane15) * 40 + lhi8) * 2);
    const uint32_t COFF = (uint32_t)(96 * 40 * 2);   // B1 = boff + COFF
    const uint32_t aoff = (uint32_t)(((ABASE + wm * 16 + lane15) * 40 + lhi8) * 2);
    const uint32_t A1OFF = (uint32_t)(64 * 40 * 2);  // A1 = aoff + A1OFF

    float acc_gh[3][2][4];
    float acc_gi[HAS_GI ? 3 : 1][2][4];
#pragma unroll
    for (int g = 0; g < 3; g++)
#pragma unroll
        for (int nh = 0; nh < 2; nh++)
#pragma unroll
            for (int i = 0; i < 4; i++) {
                acc_gh[g][nh][i] = 0.f;
                if (HAS_GI) acc_gi[g][nh][i] = 0.f;
            }

    // ---- prologue: weights for chunks 0..2 before the PDL gate ----
    stage(0, 0); stage(1, 0); stage(2, 0);
    pdl_wait();
    stage(0, 1); cp_commit();    // group0 (covers chunk0; B of 1,2 folded in)
    stage(1, 1); cp_commit();    // group1
    stage(2, 1); cp_commit();    // group2

    // ---- main loop: 16 chunks of K=32 ----
    for (int ks = 0; ks < 16; ks++) {
        if (ks < 14)      cp_wait<2>();
        else if (ks == 14) cp_wait<1>();
        else               cp_wait<0>();
        __syncthreads();
        if (ks + 3 < 16) { stage(ks + 3, 2); cp_commit(); }

        const uint32_t base = sbase + (uint32_t)((ks & 3) * SH * 2);

        uint32_t fa0[2][4], fa1[2][4], fb[2][4], fc[2][4];
        ldsm4(fa0[0], base + aoff);
        if (HAS_GI) ldsm4(fa1[0], base + aoff + A1OFF);
        ldsm4(fb[0], base + boff[0]);
        if (HAS_GI) ldsm4(fc[0], base + boff[0] + COFF);

#pragma unroll
        for (int idx = 0; idx < 6; idx++) {
            const int kk = idx / 3, g = idx % 3;
            const int p = idx & 1, q = p ^ 1;
            if (idx < 5) {
                const int nk = (idx + 1) / 3, ng_ = (idx + 1) % 3;
                ldsm4(fb[q], base + boff[ng_] + nk * 32);
                if (HAS_GI) ldsm4(fc[q], base + boff[ng_] + COFF + nk * 32);
                if (idx == 2) {
                    ldsm4(fa0[1], base + aoff + 32);
                    if (HAS_GI) ldsm4(fa1[1], base + aoff + A1OFF + 32);
                }
            }
            mma16816(acc_gh[g][0], fa0[kk], fb[p][0], fb[p][2]);
            mma16816(acc_gh[g][1], fa0[kk], fb[p][1], fb[p][3]);
            if (HAS_GI) {
                mma16816(acc_gi[g][0], fa1[kk], fc[p][0], fc[p][2]);
                mma16816(acc_gi[g][1], fa1[kk], fc[p][1], fc[p][3]);
            }
        }
    }

    // ---- epilogue: gates fully in registers (known mma C layout) ----
    const int mbase = m0 + wm * 16 + g4;
    const int nbase = n0 + wn * 16 + t4 * 2;

#pragma unroll
    for (int hm = 0; hm < 2; hm++) {
        const int row = mbase + hm * 8;
        float xv[IN_FEAT > 0 ? IN_FEAT : 1];
        if constexpr (!HAS_GI) {
            if constexpr (HAS_XFIRST) {
                xv[0] = xfirst[row];
#pragma unroll
                for (int i = 1; i < IN_FEAT; i++)
                    xv[i] = xrow[row * xstride + i - 1];
            } else {
#pragma unroll
                for (int i = 0; i < IN_FEAT; i++)
                    xv[i] = xrow[row * xstride + i];
            }
        }
#pragma unroll
        for (int nh = 0; nh < 2; nh++) {
            const int j0 = nbase + nh * 8;
            float2 hp = *(const float2*)(hprev + row * HDIM + j0);
            float2 ho;
#pragma unroll
            for (int cc = 0; cc < 2; cc++) {
                const int j = j0 + cc;
                const int ci = hm * 2 + cc;
                float gir, giz, gin;
                if constexpr (HAS_GI) {
                    gir = acc_gi[0][nh][ci] + bih[j];
                    giz = acc_gi[1][nh][ci] + bih[HDIM + j];
                    gin = acc_gi[2][nh][ci] + bih[2 * HDIM + j];
                } else {
                    gir = bih[j];
                    giz = bih[HDIM + j];
                    gin = bih[2 * HDIM + j];
                    const float* wr = WihS + j * IN_FEAT;
                    const float* wz = WihS + (HDIM + j) * IN_FEAT;
                    const float* wn_ = WihS + (2 * HDIM + j) * IN_FEAT;
#pragma unroll
                    for (int i = 0; i < IN_FEAT; i++) {
                        gir += xv[i] * wr[i];
                        giz += xv[i] * wz[i];
                        gin += xv[i] * wn_[i];
                    }
                }
                float ghr = acc_gh[0][nh][ci] + bhh[j];
                float ghz = acc_gh[1][nh][ci] + bhh[HDIM + j];
                float ghn = acc_gh[2][nh][ci] + bhh[2 * HDIM + j];
                float rg = sigmoidf_(gir + ghr);
                float zg = sigmoidf_(giz + ghz);
                float ng = tanhf(gin + rg * ghn);
                float hpv = cc ? hp.y : hp.x;
                float hv = (1.0f - zg) * ng + zg * hpv;
                if (cc) ho.y = hv; else ho.x = hv;
            }
            *(float2*)(hout + row * HDIM + j0) = ho;
            __half2 h2;
            h2.x = __float2half(ho.x);
            h2.y = __float2half(ho.y);
            *(__half2*)(hout16 + row * HDIM + j0) = h2;
        }
    }
}

#define ENC_SMEM (4 * 320 * 40 * 2)   // 102400 bytes (4-stage ring, layer1)
#define DEC_SMEM (4 * 160 * 40 * 2)   // 51200 bytes

// ---------------------------------------------------------------------------
// Fused encoder step: blocks [0,128) -> layer0 h0[t]; [128,256) -> layer1
// h1[t-1] (one-step lag makes the two halves independent).
// ---------------------------------------------------------------------------
__global__ __launch_bounds__(256, 2)
void enc_step_kernel(int t, const float* __restrict__ src,
                     const float* __restrict__ bih0, const float* __restrict__ bhh0,
                     const float* __restrict__ Wih0,
                     const float* __restrict__ bih1, const float* __restrict__ bhh1) {
    extern __shared__ __align__(16) __half dynsmem[];
    const int role = (blockIdx.x < 128) ? 0 : 1;
    const int bid = blockIdx.x & 127;
    const int m0 = (bid >> 4) * 64;
    const int n0 = (bid & 15) * 32;

    if (role == 0) {
        if (t < TSTEPS) {
            const int pw = t & 1, pr = (t + 1) & 1;
            gru_block<false, 8, false>(dynsmem, m0, n0,
                g_h0_f16[pr], g_Whh0, nullptr, nullptr,
                bih0, bhh0, Wih0, src + t * 8, TSTEPS * 8, nullptr,
                g_h0_f32[pr], g_h0_f32[pw], g_h0_f16[pw]);
        }
    } else {
        if (t >= 1) {
            const int tt = t - 1;
            const int pw = tt & 1, pr = (tt + 1) & 1;
            gru_block<true, 0, false>(dynsmem, m0, n0,
                g_h1_f16[pr], g_Whh1, g_h0_f16[tt & 1], g_Wih1,
                bih1, bhh1, nullptr, nullptr, 0, nullptr,
                g_h1_f32[pr], g_h1_f32[pw], g_h1_f16[pw]);
        }
    }
    pdl_trigger();
}

// ---------------------------------------------------------------------------
// Decoder GRU cell step (gi inline from [last_value, tf_t], 9 features)
// ---------------------------------------------------------------------------
__global__ __launch_bounds__(256, 2)
void dec_step_kernel(int s, const float* __restrict__ tf,
                     const float* __restrict__ cbih, const float* __restrict__ cbhh,
                     const float* __restrict__ cWih) {
    extern __shared__ __align__(16) __half dynsmem2[];
    const int bid = blockIdx.x;
    const int m0 = (bid >> 4) * 64;
    const int n0 = (bid & 15) * 32;
    const int pr = s & 1, pw = (s + 1) & 1;
    gru_block<false, 9, true>(dynsmem2, m0, n0,
        g_hd_f16[pr], g_cWhh, nullptr, nullptr,
        cbih, cbhh, cWih, tf + s * 8, HORIZON * 8, g_lastv,
        g_hd_f32[pr], g_hd_f32[pw], g_hd_f16[pw]);
    pdl_trigger();
}

// ---------------------------------------------------------------------------
// fc head: pred[b] = hidden[b] . fc_W + fc_b ; also feeds next last_value
// ---------------------------------------------------------------------------
__global__ __launch_bounds__(256)
void fc_kernel(int s, const float* __restrict__ fcW, const float* __restrict__ fcb,
               float* __restrict__ out) {
    pdl_wait();
    const int b = blockIdx.x * 8 + (threadIdx.x >> 5);
    const int lane = threadIdx.x & 31;
    const float* h = g_hd_f32[(s + 1) & 1] + b * HDIM;
    float sum = 0.f;
#pragma unroll
    for (int k = lane; k < HDIM; k += 32) sum += h[k] * fcW[k];
#pragma unroll
    for (int o = 16; o; o >>= 1) sum += __shfl_xor_sync(0xffffffffu, sum, o);
    if (lane == 0) {
        float p = sum + fcb[0];
        out[b * HORIZON + s] = p;
        g_lastv[b] = p;
    }
    pdl_trigger();
}

// ---------------------------------------------------------------------------
// dec0 linear: hidden0 = h1[T-1] @ dec0_Wᵀ + dec0_b  (one-time, fp32 SIMT)
// ---------------------------------------------------------------------------
__global__ __launch_bounds__(256)
void dec0_kernel(const float* __restrict__ W, const float* __restrict__ bias) {
    pdl_wait();
    __shared__ float As[64][17];
    __shared__ float Ws[64][17];
    const float* A = g_h1_f32[(TSTEPS - 1) & 1];
    const int m0 = blockIdx.y * 64, n0 = blockIdx.x * 64;
    const int tx = threadIdx.x & 15, ty = threadIdx.x >> 4;
    float acc[4][4] = {};
    for (int k0 = 0; k0 < HDIM; k0 += 16) {
#pragma unroll
        for (int i = 0; i < 4; i++) {
            int idx = threadIdx.x + i * 256;
            int r = idx >> 4, c = idx & 15;
            As[r][c] = A[(m0 + r) * HDIM + k0 + c];
            Ws[r][c] = W[(n0 + r) * HDIM + k0 + c];
        }
        __syncthreads();
#pragma unroll
        for (int kk = 0; kk < 16; kk++) {
            float a[4], w[4];
#pragma unroll
            for (int i = 0; i < 4; i++) { a[i] = As[ty * 4 + i][kk]; w[i] = Ws[tx * 4 + i][kk]; }
#pragma unroll
            for (int i = 0; i < 4; i++)
#pragma unroll
                for (int j = 0; j < 4; j++) acc[i][j] += a[i] * w[j];
        }
        __syncthreads();
    }
#pragma unroll
    for (int i = 0; i < 4; i++)
#pragma unroll
        for (int j = 0; j < 4; j++) {
            int m = m0 + ty * 4 + i, n = n0 + tx * 4 + j;
            float v = acc[i][j] + bias[n];
            g_hd_f32[0][m * HDIM + n] = v;
            g_hd_f16[0][m * HDIM + n] = __float2half(v);
        }
    pdl_trigger();
}

// ---------------------------------------------------------------------------
// setup kernels
// ---------------------------------------------------------------------------
__global__ void convert_weights_kernel(const float* __restrict__ Whh0,
                                       const float* __restrict__ Wih1,
                                       const float* __restrict__ Whh1,
                                       const float* __restrict__ cWhh) {
    int i = blockIdx.x * blockDim.x + threadIdx.x;
    if (i < G3H * HDIM) {
        g_Whh0[i] = __float2half(Whh0[i]);
        g_Wih1[i] = __float2half(Wih1[i]);
        g_Whh1[i] = __float2half(Whh1[i]);
        g_cWhh[i] = __float2half(cWhh[i]);
    }
}

__global__ void init_kernel(const float* __restrict__ src) {
    int i = blockIdx.x * blockDim.x + threadIdx.x;
    if (i < BATCH * HDIM) {
        g_h0_f32[1][i] = 0.f;
        g_h1_f32[1][i] = 0.f;
        g_h0_f16[1][i] = __float2half(0.f);
        g_h1_f16[1][i] = __float2half(0.f);
    }
    if (i < BATCH) g_lastv[i] = src[i * (TSTEPS * 8) + (TSTEPS - 1) * 8];
}

// ---------------------------------------------------------------------------
// PDL launch helper
// ---------------------------------------------------------------------------
static void launch_pdl(const void* func, dim3 grid, dim3 block, size_t smem,
                       void** args) {
    cudaLaunchConfig_t cfg = {};
    cfg.gridDim = grid;
    cfg.blockDim = block;
    cfg.dynamicSmemBytes = smem;
    cfg.stream = 0;
    cudaLaunchAttribute at[1];
    at[0].id = cudaLaunchAttributeProgrammaticStreamSerialization;
    at[0].val.programmaticStreamSerializationAllowed = 1;
    cfg.attrs = at;
    cfg.numAttrs = 1;
    cudaLaunchKernelExC(&cfg, func, args);
}

// ---------------------------------------------------------------------------
extern "C" void kernel_launch(void* const* d_in, const int* in_sizes, int n_in,
                              void* d_out, int out_size) {
    const float* src   = (const float*)d_in[0];
    const float* tf    = (const float*)d_in[1];
    const float* Wih0  = (const float*)d_in[2];
    const float* Whh0  = (const float*)d_in[3];
    const float* bih0  = (const float*)d_in[4];
    const float* bhh0  = (const float*)d_in[5];
    const float* Wih1  = (const float*)d_in[6];
    const float* Whh1  = (const float*)d_in[7];
    const float* bih1  = (const float*)d_in[8];
    const float* bhh1  = (const float*)d_in[9];
    const float* dec0W = (const float*)d_in[10];
    const float* dec0b = (const float*)d_in[11];
    const float* cWih  = (const float*)d_in[12];
    const float* cWhh  = (const float*)d_in[13];
    const float* cbih  = (const float*)d_in[14];
    const float* cbhh  = (const float*)d_in[15];
    const float* fcW   = (const float*)d_in[16];
    const float* fcb   = (const float*)d_in[17];
    float* out = (float*)d_out;

    cudaFuncSetAttribute(enc_step_kernel,
                         cudaFuncAttributeMaxDynamicSharedMemorySize, ENC_SMEM);
    cudaFuncSetAttribute(dec_step_kernel,
                         cudaFuncAttributeMaxDynamicSharedMemorySize, DEC_SMEM);

    convert_weights_kernel<<<(G3H * HDIM + 255) / 256, 256>>>(Whh0, Wih1, Whh1, cWhh);
    init_kernel<<<(BATCH * HDIM + 255) / 256, 256>>>(src);

    // Encoder: T+1 fused launches with PDL chaining
    for (int t = 0; t <= TSTEPS; t++) {
        int tv = t;
        void* args[] = { &tv, (void*)&src, (void*)&bih0, (void*)&bhh0,
                         (void*)&Wih0, (void*)&bih1, (void*)&bhh1 };
        launch_pdl((const void*)enc_step_kernel, dim3(256), dim3(256),
                   ENC_SMEM, args);
    }

    // Decoder init + 48 steps, all PDL-chained
    {
        void* args[] = { (void*)&dec0W, (void*)&dec0b };
        launch_pdl((const void*)dec0_kernel, dim3(8, 8), dim3(256), 0, args);
    }
    for (int s = 0; s < HORIZON; s++) {
        int sv = s;
        {
            void* args[] = { &sv, (void*)&tf, (void*)&cbih, (void*)&cbhh,
                             (void*)&cWih };
            launch_pdl((const void*)dec_step_kernel, dim3(128), dim3(256),
                       DEC_SMEM, args);
        }
        {
            void* args[] = { &sv, (void*)&fcW, (void*)&fcb, (void*)&out };
            launch_pdl((const void*)fc_kernel, dim3(64), dim3(256), 0, args);
        }
    }
}

// round 15
// speedup vs baseline: 1.1970x; 1.1970x over previous
#include <cuda_runtime.h>
#include <cuda_fp16.h>
#include <cstdint>

// ---------------------------------------------------------------------------
// Seq2SeqForecast: 2-layer GRU encoder (B=512, T=336, H=512) + 48-step GRU
// decoder with scalar head.
//
// R14 = R12 (best, 6380us; R13 inner-loop rebuild regressed and is reverted)
//       + fc head fused into dec_step epilogue:
//  * init_kernel pre-fills out with fc_b; dec_step blocks atomicAdd their
//    64x32 partial h.fcW dots straight from registers -> 48 fc launches gone.
//  * next dec_step reads last_value from out[:, s-1] (PDL visibility).
// Encoder path byte-identical to R12.
// ---------------------------------------------------------------------------

#define HDIM   512
#define BATCH  512
#define TSTEPS 336
#define HORIZON 48
#define G3H    (3 * HDIM)          // 1536

// fp16 weight copies
__device__ __half g_Whh0[G3H * HDIM];
__device__ __half g_Wih1[G3H * HDIM];
__device__ __half g_Whh1[G3H * HDIM];
__device__ __half g_cWhh[G3H * HDIM];

// hidden-state ping-pong buffers (fp32 master + fp16 shadow for MMA)
__device__ float  g_h0_f32[2][BATCH * HDIM];
__device__ __half g_h0_f16[2][BATCH * HDIM];
__device__ float  g_h1_f32[2][BATCH * HDIM];
__device__ __half g_h1_f16[2][BATCH * HDIM];
__device__ float  g_hd_f32[2][BATCH * HDIM];
__device__ __half g_hd_f16[2][BATCH * HDIM];
__device__ float  g_lastv[BATCH];

// ---------------------------------------------------------------------------
// helpers
// ---------------------------------------------------------------------------
__device__ __forceinline__ void mma16816(float (&c)[4], const uint32_t (&a)[4],
                                         uint32_t b0, uint32_t b1) {
    asm volatile(
        "mma.sync.aligned.m16n8k16.row.col.f32.f16.f16.f32 "
        "{%0,%1,%2,%3}, {%4,%5,%6,%7}, {%8,%9}, {%0,%1,%2,%3};\n"
        : "+f"(c[0]), "+f"(c[1]), "+f"(c[2]), "+f"(c[3])
        : "r"(a[0]), "r"(a[1]), "r"(a[2]), "r"(a[3]), "r"(b0), "r"(b1));
}

__device__ __forceinline__ void ldsm4(uint32_t (&r)[4], uint32_t saddr) {
    asm volatile(
        "ldmatrix.sync.aligned.m8n8.x4.shared.b16 {%0,%1,%2,%3}, [%4];\n"
        : "=r"(r[0]), "=r"(r[1]), "=r"(r[2]), "=r"(r[3]) : "r"(saddr));
}

__device__ __forceinline__ float sigmoidf_(float x) {
    return 1.0f / (1.0f + expf(-x));
}

__device__ __forceinline__ void cp16(uint32_t dst, const void* src) {
    asm volatile("cp.async.cg.shared.global [%0], [%1], 16;\n"
                 :: "r"(dst), "l"(src));
}
__device__ __forceinline__ void cp_commit() {
    asm volatile("cp.async.commit_group;\n");
}
template <int N>
__device__ __forceinline__ void cp_wait() {
    asm volatile("cp.async.wait_group %0;\n" :: "n"(N));
}

// PDL: no-ops when the launch lacks the programmatic-serialization attribute.
__device__ __forceinline__ void pdl_wait() {
    asm volatile("griddepcontrol.wait;" ::: "memory");
}
__device__ __forceinline__ void pdl_trigger() {
    asm volatile("griddepcontrol.launch_dependents;" ::: "memory");
}

// ---------------------------------------------------------------------------
// Core GRU tile: block computes a 64(batch) x 32(hidden) tile of h_new.
// gh = h_prev @ Wghᵀ (+bhh) always via MMA.
// gi either via MMA (HAS_GI: layer1) or inline small dot (IN_FEAT = 8 or 9).
// Double-buffered smem (stride BSTRIDE halves per buffer); per-buffer layout
// (row stride 72 halves): As0[64] Bs0[96] [As1[64] Bs1[96] if HAS_GI].
// PDLW: stage chunk-0 WEIGHTS before griddepcontrol.wait.
// DO_FC: accumulate partial h.fcW in epilogue, atomicAdd into outp (row
// stride HORIZON).
// ---------------------------------------------------------------------------
template <bool HAS_GI, int IN_FEAT, bool HAS_XFIRST, int BSTRIDE, bool PDLW,
          bool DO_FC>
__device__ __forceinline__ void gru_block(
    __half* __restrict__ smem, int m0, int n0,
    const __half* __restrict__ Agh, const __half* __restrict__ Wgh,
    const __half* __restrict__ Agi, const __half* __restrict__ Wgi,
    const float* __restrict__ bih, const float* __restrict__ bhh,
    const float* __restrict__ WihS,  // [1536 x IN_FEAT] small input weights
    const float* __restrict__ xrow, int xstride,
    const float* __restrict__ xfirst, int xfstride,
    const float* __restrict__ hprev, float* __restrict__ hout,
    __half* __restrict__ hout16,
    const float* __restrict__ fcW, float* __restrict__ outp) {

    const int tid  = threadIdx.x;
    const int lane = tid & 31;
    const int wid  = tid >> 5;       // 8 warps
    const int wm   = wid >> 1;       // 4 warps along M
    const int wn   = wid & 1;        // 2 warps along N
    const int g4   = lane >> 2;      // 0..7
    const int t4   = lane & 3;       // 0..3

    // ---- cp.async staging setup ----
    const int r8 = tid >> 3;         // 0..31
    const int c8 = tid & 7;          // 0..7 (uint4 within 64-half k-chunk)
    const uint32_t sbase = (uint32_t)__cvta_generic_to_shared(smem);
    const uint32_t sA  = sbase + (uint32_t)((r8 * 72 + c8 * 8) * 2);
    const uint32_t sB  = sbase + (uint32_t)((64 * 72 + r8 * 72 + c8 * 8) * 2);
    const __half* pA0   = Agh + (m0 + r8) * HDIM + c8 * 8;
    const __half* pB0_0 = Wgh + (0 * HDIM + n0 + r8) * HDIM + c8 * 8;
    const __half* pB0_1 = Wgh + (1 * HDIM + n0 + r8) * HDIM + c8 * 8;
    const __half* pB0_2 = Wgh + (2 * HDIM + n0 + r8) * HDIM + c8 * 8;
    const __half* pA1   = HAS_GI ? Agi + (m0 + r8) * HDIM + c8 * 8 : nullptr;
    const __half* pB1_0 = HAS_GI ? Wgi + (0 * HDIM + n0 + r8) * HDIM + c8 * 8 : nullptr;
    const __half* pB1_1 = HAS_GI ? Wgi + (1 * HDIM + n0 + r8) * HDIM + c8 * 8 : nullptr;
    const __half* pB1_2 = HAS_GI ? Wgi + (2 * HDIM + n0 + r8) * HDIM + c8 * 8 : nullptr;

    auto stageB = [&](int ks) {
        const uint32_t bo = (uint32_t)((ks & 1) * BSTRIDE * 2);
        const int ko = ks * 64;
        cp16(sB + bo, pB0_0 + ko);
        cp16(sB + bo + 32 * 72 * 2, pB0_1 + ko);
        cp16(sB + bo + 64 * 72 * 2, pB0_2 + ko);
        if (HAS_GI) {
            const uint32_t bo1 = bo + 160 * 72 * 2;
            cp16(sB + bo1, pB1_0 + ko);
            cp16(sB + bo1 + 32 * 72 * 2, pB1_1 + ko);
            cp16(sB + bo1 + 64 * 72 * 2, pB1_2 + ko);
        }
    };
    auto stageA = [&](int ks) {
        const uint32_t bo = (uint32_t)((ks & 1) * BSTRIDE * 2);
        const int ko = ks * 64;
        cp16(sA + bo, pA0 + ko);
        cp16(sA + bo + 32 * 72 * 2, pA0 + 32 * HDIM + ko);
        if (HAS_GI) {
            const uint32_t bo1 = bo + 160 * 72 * 2;
            cp16(sA + bo1, pA1 + ko);
            cp16(sA + bo1 + 32 * 72 * 2, pA1 + 32 * HDIM + ko);
        }
    };

    float acc_gh[3][2][4];
    float acc_gi[3][2][4];
#pragma unroll
    for (int g = 0; g < 3; g++)
#pragma unroll
        for (int nh = 0; nh < 2; nh++)
#pragma unroll
            for (int i = 0; i < 4; i++) {
                acc_gh[g][nh][i] = 0.f;
                if (HAS_GI) acc_gi[g][nh][i] = 0.f;
            }

    // ldmatrix per-lane addressing (x4 fragment order matches mma A/B).
    const int lane15 = lane & 15;
    const int lhi8   = (lane >> 4) * 8;
    const uint32_t aoff = (uint32_t)(((wm * 16 + lane15) * 72 + lhi8) * 2);
    uint32_t boff[3];
#pragma unroll
    for (int g = 0; g < 3; g++)
        boff[g] = (uint32_t)(((64 + g * 32 + wn * 16 + lane15) * 72 + lhi8) * 2);
    const uint32_t GIOFF = (uint32_t)(160 * 72 * 2);

    // chunk 0: weights before the PDL dependency gate, A tiles after.
    stageB(0); cp_commit();
    if (PDLW) pdl_wait();
    stageA(0); cp_commit();

    for (int ks = 0; ks < 8; ks++) {
        if (ks < 7) { stageA(ks + 1); stageB(ks + 1); cp_commit(); cp_wait<1>(); }
        else        { cp_wait<0>(); }
        __syncthreads();

        const uint32_t base = sbase + (uint32_t)((ks & 1) * BSTRIDE * 2);

#pragma unroll
        for (int kk = 0; kk < 64; kk += 16) {
            uint32_t a0[4], a1[4];
            ldsm4(a0, base + aoff + kk * 2);
            if (HAS_GI) ldsm4(a1, base + GIOFF + aoff + kk * 2);
#pragma unroll
            for (int g = 0; g < 3; g++) {
                uint32_t b[4];
                ldsm4(b, base + boff[g] + kk * 2);
                mma16816(acc_gh[g][0], a0, b[0], b[2]);
                mma16816(acc_gh[g][1], a0, b[1], b[3]);
                if (HAS_GI) {
                    uint32_t c[4];
                    ldsm4(c, base + GIOFF + boff[g] + kk * 2);
                    mma16816(acc_gi[g][0], a1, c[0], c[2]);
                    mma16816(acc_gi[g][1], a1, c[1], c[3]);
                }
            }
        }
        __syncthreads();
    }

    // ---- epilogue: gates fully in registers (known mma C layout) ----
    const int mbase = m0 + wm * 16 + g4;
    const int nbase = n0 + wn * 16 + t4 * 2;

    float fcp[2] = {0.f, 0.f};

#pragma unroll
    for (int hm = 0; hm < 2; hm++) {
        const int row = mbase + hm * 8;
        float xv[IN_FEAT > 0 ? IN_FEAT : 1];
        if constexpr (!HAS_GI) {
            if constexpr (HAS_XFIRST) {
                xv[0] = xfirst[(size_t)row * xfstride];
#pragma unroll
                for (int i = 1; i < IN_FEAT; i++)
                    xv[i] = xrow[row * xstride + i - 1];
            } else {
#pragma unroll
                for (int i = 0; i < IN_FEAT; i++)
                    xv[i] = xrow[row * xstride + i];
            }
        }
#pragma unroll
        for (int nh = 0; nh < 2; nh++) {
            const int j0 = nbase + nh * 8;
            float2 hp = *(const float2*)(hprev + row * HDIM + j0);
            float2 ho;
#pragma unroll
            for (int cc = 0; cc < 2; cc++) {
                const int j = j0 + cc;
                const int ci = hm * 2 + cc;
                float gir, giz, gin;
                if constexpr (HAS_GI) {
                    gir = acc_gi[0][nh][ci] + bih[j];
                    giz = acc_gi[1][nh][ci] + bih[HDIM + j];
                    gin = acc_gi[2][nh][ci] + bih[2 * HDIM + j];
                } else {
                    gir = bih[j];
                    giz = bih[HDIM + j];
                    gin = bih[2 * HDIM + j];
                    const float* wr = WihS + j * IN_FEAT;
                    const float* wz = WihS + (HDIM + j) * IN_FEAT;
                    const float* wn_ = WihS + (2 * HDIM + j) * IN_FEAT;
#pragma unroll
                    for (int i = 0; i < IN_FEAT; i++) {
                        gir += xv[i] * wr[i];
                        giz += xv[i] * wz[i];
                        gin += xv[i] * wn_[i];
                    }
                }
                float ghr = acc_gh[0][nh][ci] + bhh[j];
                float ghz = acc_gh[1][nh][ci] + bhh[HDIM + j];
                float ghn = acc_gh[2][nh][ci] + bhh[2 * HDIM + j];
                float rg = sigmoidf_(gir + ghr);
                float zg = sigmoidf_(giz + ghz);
                float ng = tanhf(gin + rg * ghn);
                float hpv = cc ? hp.y : hp.x;
                float hv = (1.0f - zg) * ng + zg * hpv;
                if (cc) ho.y = hv; else ho.x = hv;
            }
            *(float2*)(hout + row * HDIM + j0) = ho;
            __half2 h2;
            h2.x = __float2half(ho.x);
            h2.y = __float2half(ho.y);
            *(__half2*)(hout16 + row * HDIM + j0) = h2;
            if constexpr (DO_FC)
                fcp[hm] += ho.x * fcW[j0] + ho.y * fcW[j0 + 1];
        }
    }

    if constexpr (DO_FC) {
#pragma unroll
        for (int hm = 0; hm < 2; hm++)
            atomicAdd(outp + (size_t)(mbase + hm * 8) * HORIZON, fcp[hm]);
    }
}

#define ENC_BSTRIDE (320 * 72)
#define DEC_BSTRIDE (160 * 72)
#define ENC_SMEM    (2 * ENC_BSTRIDE * 2)   // 92160 bytes
#define DEC_SMEM    (2 * DEC_BSTRIDE * 2)   // 46080 bytes

// ---------------------------------------------------------------------------
// Fused encoder step: blocks [0,128) -> layer0 h0[t]; [128,256) -> layer1
// h1[t-1] (one-step lag makes the two halves independent).
// ---------------------------------------------------------------------------
__global__ __launch_bounds__(256, 2)
void enc_step_kernel(int t, const float* __restrict__ src,
                     const float* __restrict__ bih0, const float* __restrict__ bhh0,
                     const float* __restrict__ Wih0,
                     const float* __restrict__ bih1, const float* __restrict__ bhh1) {
    extern __shared__ __align__(16) __half dynsmem[];
    const int role = (blockIdx.x < 128) ? 0 : 1;
    const int bid = blockIdx.x & 127;
    const int m0 = (bid >> 4) * 64;
    const int n0 = (bid & 15) * 32;

    if (role == 0) {
        if (t < TSTEPS) {
            const int pw = t & 1, pr = (t + 1) & 1;   // h0[t-1] at parity (t-1)&1
            gru_block<false, 8, false, ENC_BSTRIDE, true, false>(dynsmem, m0, n0,
                g_h0_f16[pr], g_Whh0, nullptr, nullptr,
                bih0, bhh0, Wih0, src + t * 8, TSTEPS * 8, nullptr, 1,
                g_h0_f32[pr], g_h0_f32[pw], g_h0_f16[pw], nullptr, nullptr);
        }
    } else {
        if (t >= 1) {
            const int tt = t - 1;                     // computing h1[tt]
            const int pw = tt & 1, pr = (tt + 1) & 1; // h1[tt-1] parity
            gru_block<true, 0, false, ENC_BSTRIDE, true, false>(dynsmem, m0, n0,
                g_h1_f16[pr], g_Whh1, g_h0_f16[tt & 1], g_Wih1,
                bih1, bhh1, nullptr, nullptr, 0, nullptr, 1,
                g_h1_f32[pr], g_h1_f32[pw], g_h1_f16[pw], nullptr, nullptr);
        }
    }
    pdl_trigger();
}

// ---------------------------------------------------------------------------
// Decoder GRU cell step (gi inline from [last_value, tf_t], 9 features)
// with fused fc head: blocks atomicAdd partial h.fcW into out[:, s]
// (pre-initialized with fc_b). last_value for s>0 is read from out[:, s-1].
// ---------------------------------------------------------------------------
__global__ __launch_bounds__(256, 2)
void dec_step_kernel(int s, const float* __restrict__ tf,
                     const float* __restrict__ cbih, const float* __restrict__ cbhh,
                     const float* __restrict__ cWih,
                     const float* __restrict__ fcW, float* __restrict__ out) {
    extern __shared__ __align__(16) __half dynsmem2[];
    const int bid = blockIdx.x;
    const int m0 = (bid >> 4) * 64;
    const int n0 = (bid & 15) * 32;
    const int pr = s & 1, pw = (s + 1) & 1;
    const float* lastsrc = (s == 0) ? g_lastv : (out + (s - 1));
    const int xfstr = (s == 0) ? 1 : HORIZON;
    gru_block<false, 9, true, DEC_BSTRIDE, true, true>(dynsmem2, m0, n0,
        g_hd_f16[pr], g_cWhh, nullptr, nullptr,
        cbih, cbhh, cWih, tf + s * 8, HORIZON * 8, lastsrc, xfstr,
        g_hd_f32[pr], g_hd_f32[pw], g_hd_f16[pw], fcW, out + s);
    pdl_trigger();
}

// ---------------------------------------------------------------------------
// dec0 linear: hidden0 = h1[T-1] @ dec0_Wᵀ + dec0_b  (one-time, fp32 SIMT)
// ---------------------------------------------------------------------------
__global__ __launch_bounds__(256)
void dec0_kernel(const float* __restrict__ W, const float* __restrict__ bias) {
    pdl_wait();
    __shared__ float As[64][17];
    __shared__ float Ws[64][17];
    const float* A = g_h1_f32[(TSTEPS - 1) & 1];
    const int m0 = blockIdx.y * 64, n0 = blockIdx.x * 64;
    const int tx = threadIdx.x & 15, ty = threadIdx.x >> 4;
    float acc[4][4] = {};
    for (int k0 = 0; k0 < HDIM; k0 += 16) {
#pragma unroll
        for (int i = 0; i < 4; i++) {
            int idx = threadIdx.x + i * 256;
            int r = idx >> 4, c = idx & 15;
            As[r][c] = A[(m0 + r) * HDIM + k0 + c];
            Ws[r][c] = W[(n0 + r) * HDIM + k0 + c];
        }
        __syncthreads();
#pragma unroll
        for (int kk = 0; kk < 16; kk++) {
            float a[4], w[4];
#pragma unroll
            for (int i = 0; i < 4; i++) { a[i] = As[ty * 4 + i][kk]; w[i] = Ws[tx * 4 + i][kk]; }
#pragma unroll
            for (int i = 0; i < 4; i++)
#pragma unroll
                for (int j = 0; j < 4; j++) acc[i][j] += a[i] * w[j];
        }
        __syncthreads();
    }
#pragma unroll
    for (int i = 0; i < 4; i++)
#pragma unroll
        for (int j = 0; j < 4; j++) {
            int m = m0 + ty * 4 + i, n = n0 + tx * 4 + j;
            float v = acc[i][j] + bias[n];
            g_hd_f32[0][m * HDIM + n] = v;
            g_hd_f16[0][m * HDIM + n] = __float2half(v);
        }
    pdl_trigger();
}

// ---------------------------------------------------------------------------
// setup kernels
// ---------------------------------------------------------------------------
__global__ void convert_weights_kernel(const float* __restrict__ Whh0,
                                       const float* __restrict__ Wih1,
                                       const float* __restrict__ Whh1,
                                       const float* __restrict__ cWhh) {
    int i = blockIdx.x * blockDim.x + threadIdx.x;
    if (i < G3H * HDIM) {
        g_Whh0[i] = __float2half(Whh0[i]);
        g_Wih1[i] = __float2half(Wih1[i]);
        g_Whh1[i] = __float2half(Whh1[i]);
        g_cWhh[i] = __float2half(cWhh[i]);
    }
}

__global__ void init_kernel(const float* __restrict__ src,
                            const float* __restrict__ fcb,
                            float* __restrict__ out) {
    int i = blockIdx.x * blockDim.x + threadIdx.x;
    if (i < BATCH * HDIM) {
        g_h0_f32[1][i] = 0.f;
        g_h1_f32[1][i] = 0.f;
        g_h0_f16[1][i] = __float2half(0.f);
        g_h1_f16[1][i] = __float2half(0.f);
    }
    if (i < BATCH) g_lastv[i] = src[i * (TSTEPS * 8) + (TSTEPS - 1) * 8];
    if (i < BATCH * HORIZON) out[i] = fcb[0];   // fc bias pre-load
}

// ---------------------------------------------------------------------------
// PDL launch helper
// ---------------------------------------------------------------------------
static void launch_pdl(const void* func, dim3 grid, dim3 block, size_t smem,
                       void** args) {
    cudaLaunchConfig_t cfg = {};
    cfg.gridDim = grid;
    cfg.blockDim = block;
    cfg.dynamicSmemBytes = smem;
    cfg.stream = 0;
    cudaLaunchAttribute at[1];
    at[0].id = cudaLaunchAttributeProgrammaticStreamSerialization;
    at[0].val.programmaticStreamSerializationAllowed = 1;
    cfg.attrs = at;
    cfg.numAttrs = 1;
    cudaLaunchKernelExC(&cfg, func, args);
}

// ---------------------------------------------------------------------------
extern "C" void kernel_launch(void* const* d_in, const int* in_sizes, int n_in,
                              void* d_out, int out_size) {
    const float* src   = (const float*)d_in[0];
    const float* tf    = (const float*)d_in[1];
    const float* Wih0  = (const float*)d_in[2];
    const float* Whh0  = (const float*)d_in[3];
    const float* bih0  = (const float*)d_in[4];
    const float* bhh0  = (const float*)d_in[5];
    const float* Wih1  = (const float*)d_in[6];
    const float* Whh1  = (const float*)d_in[7];
    const float* bih1  = (const float*)d_in[8];
    const float* bhh1  = (const float*)d_in[9];
    const float* dec0W = (const float*)d_in[10];
    const float* dec0b = (const float*)d_in[11];
    const float* cWih  = (const float*)d_in[12];
    const float* cWhh  = (const float*)d_in[13];
    const float* cbih  = (const float*)d_in[14];
    const float* cbhh  = (const float*)d_in[15];
    const float* fcW   = (const float*)d_in[16];
    const float* fcb   = (const float*)d_in[17];
    float* out = (float*)d_out;

    cudaFuncSetAttribute(enc_step_kernel,
                         cudaFuncAttributeMaxDynamicSharedMemorySize, ENC_SMEM);
    cudaFuncSetAttribute(dec_step_kernel,
                         cudaFuncAttributeMaxDynamicSharedMemorySize, DEC_SMEM);

    convert_weights_kernel<<<(G3H * HDIM + 255) / 256, 256>>>(Whh0, Wih1, Whh1, cWhh);
    init_kernel<<<(BATCH * HDIM + 255) / 256, 256>>>(src, fcb, out);

    // Encoder: T+1 fused launches with PDL chaining
    for (int t = 0; t <= TSTEPS; t++) {
        int tv = t;
        void* args[] = { &tv, (void*)&src, (void*)&bih0, (void*)&bhh0,
                         (void*)&Wih0, (void*)&bih1, (void*)&bhh1 };
        launch_pdl((const void*)enc_step_kernel, dim3(256), dim3(256),
                   ENC_SMEM, args);
    }

    // Decoder init + 48 steps (fc fused into dec_step), all PDL-chained
    {
        void* args[] = { (void*)&dec0W, (void*)&dec0b };
        launch_pdl((const void*)dec0_kernel, dim3(8, 8), dim3(256), 0, args);
    }
    for (int s = 0; s < HORIZON; s++) {
        int sv = s;
        void* args[] = { &sv, (void*)&tf, (void*)&cbih, (void*)&cbhh,
                         (void*)&cWih, (void*)&fcW, (void*)&out };
        launch_pdl((const void*)dec_step_kernel, dim3(128), dim3(256),
                   DEC_SMEM, args);
    }
}

// round 16
// speedup vs baseline: 1.2007x; 1.0031x over previous
#include <cuda_runtime.h>
#include <cuda_fp16.h>
#include <cstdint>

// ---------------------------------------------------------------------------
// Seq2SeqForecast: 2-layer GRU encoder (B=512, T=336, H=512) + 48-step GRU
// decoder with scalar head.
//
// R14 = R12 (best, 6380us; R13 inner-loop rebuild regressed and is reverted)
//       + fc head fused into dec_step epilogue:
//  * init_kernel pre-fills out with fc_b; dec_step blocks atomicAdd their
//    64x32 partial h.fcW dots straight from registers -> 48 fc launches gone.
//  * next dec_step reads last_value from out[:, s-1] (PDL visibility).
// Encoder path byte-identical to R12.
// ---------------------------------------------------------------------------

#define HDIM   512
#define BATCH  512
#define TSTEPS 336
#define HORIZON 48
#define G3H    (3 * HDIM)          // 1536

// fp16 weight copies
__device__ __half g_Whh0[G3H * HDIM];
__device__ __half g_Wih1[G3H * HDIM];
__device__ __half g_Whh1[G3H * HDIM];
__device__ __half g_cWhh[G3H * HDIM];

// hidden-state ping-pong buffers (fp32 master + fp16 shadow for MMA)
__device__ float  g_h0_f32[2][BATCH * HDIM];
__device__ __half g_h0_f16[2][BATCH * HDIM];
__device__ float  g_h1_f32[2][BATCH * HDIM];
__device__ __half g_h1_f16[2][BATCH * HDIM];
__device__ float  g_hd_f32[2][BATCH * HDIM];
__device__ __half g_hd_f16[2][BATCH * HDIM];
__device__ float  g_lastv[BATCH];

// ---------------------------------------------------------------------------
// helpers
// ---------------------------------------------------------------------------
__device__ __forceinline__ void mma16816(float (&c)[4], const uint32_t (&a)[4],
                                         uint32_t b0, uint32_t b1) {
    asm volatile(
        "mma.sync.aligned.m16n8k16.row.col.f32.f16.f16.f32 "
        "{%0,%1,%2,%3}, {%4,%5,%6,%7}, {%8,%9}, {%0,%1,%2,%3};\n"
        : "+f"(c[0]), "+f"(c[1]), "+f"(c[2]), "+f"(c[3])
        : "r"(a[0]), "r"(a[1]), "r"(a[2]), "r"(a[3]), "r"(b0), "r"(b1));
}

__device__ __forceinline__ void ldsm4(uint32_t (&r)[4], uint32_t saddr) {
    asm volatile(
        "ldmatrix.sync.aligned.m8n8.x4.shared.b16 {%0,%1,%2,%3}, [%4];\n"
        : "=r"(r[0]), "=r"(r[1]), "=r"(r[2]), "=r"(r[3]) : "r"(saddr));
}

__device__ __forceinline__ float sigmoidf_(float x) {
    return 1.0f / (1.0f + expf(-x));
}

__device__ __forceinline__ void cp16(uint32_t dst, const void* src) {
    asm volatile("cp.async.cg.shared.global [%0], [%1], 16;\n"
                 :: "r"(dst), "l"(src));
}
__device__ __forceinline__ void cp_commit() {
    asm volatile("cp.async.commit_group;\n");
}
template <int N>
__device__ __forceinline__ void cp_wait() {
    asm volatile("cp.async.wait_group %0;\n" :: "n"(N));
}

// PDL: no-ops when the launch lacks the programmatic-serialization attribute.
__device__ __forceinline__ void pdl_wait() {
    asm volatile("griddepcontrol.wait;" ::: "memory");
}
__device__ __forceinline__ void pdl_trigger() {
    asm volatile("griddepcontrol.launch_dependents;" ::: "memory");
}

// ---------------------------------------------------------------------------
// Core GRU tile: block computes a 64(batch) x 32(hidden) tile of h_new.
// gh = h_prev @ Wghᵀ (+bhh) always via MMA.
// gi either via MMA (HAS_GI: layer1) or inline small dot (IN_FEAT = 8 or 9).
// Double-buffered smem (stride BSTRIDE halves per buffer); per-buffer layout
// (row stride 72 halves): As0[64] Bs0[96] [As1[64] Bs1[96] if HAS_GI].
// PDLW: stage chunk-0 WEIGHTS before griddepcontrol.wait.
// DO_FC: accumulate partial h.fcW in epilogue, atomicAdd into outp (row
// stride HORIZON).
// ---------------------------------------------------------------------------
template <bool HAS_GI, int IN_FEAT, bool HAS_XFIRST, int BSTRIDE, bool PDLW,
          bool DO_FC>
__device__ __forceinline__ void gru_block(
    __half* __restrict__ smem, int m0, int n0,
    const __half* __restrict__ Agh, const __half* __restrict__ Wgh,
    const __half* __restrict__ Agi, const __half* __restrict__ Wgi,
    const float* __restrict__ bih, const float* __restrict__ bhh,
    const float* __restrict__ WihS,  // [1536 x IN_FEAT] small input weights
    const float* __restrict__ xrow, int xstride,
    const float* __restrict__ xfirst, int xfstride,
    const float* __restrict__ hprev, float* __restrict__ hout,
    __half* __restrict__ hout16,
    const float* __restrict__ fcW, float* __restrict__ outp) {

    const int tid  = threadIdx.x;
    const int lane = tid & 31;
    const int wid  = tid >> 5;       // 8 warps
    const int wm   = wid >> 1;       // 4 warps along M
    const int wn   = wid & 1;        // 2 warps along N
    const int g4   = lane >> 2;      // 0..7
    const int t4   = lane & 3;       // 0..3

    // ---- cp.async staging setup ----
    const int r8 = tid >> 3;         // 0..31
    const int c8 = tid & 7;          // 0..7 (uint4 within 64-half k-chunk)
    const uint32_t sbase = (uint32_t)__cvta_generic_to_shared(smem);
    const uint32_t sA  = sbase + (uint32_t)((r8 * 72 + c8 * 8) * 2);
    const uint32_t sB  = sbase + (uint32_t)((64 * 72 + r8 * 72 + c8 * 8) * 2);
    const __half* pA0   = Agh + (m0 + r8) * HDIM + c8 * 8;
    const __half* pB0_0 = Wgh + (0 * HDIM + n0 + r8) * HDIM + c8 * 8;
    const __half* pB0_1 = Wgh + (1 * HDIM + n0 + r8) * HDIM + c8 * 8;
    const __half* pB0_2 = Wgh + (2 * HDIM + n0 + r8) * HDIM + c8 * 8;
    const __half* pA1   = HAS_GI ? Agi + (m0 + r8) * HDIM + c8 * 8 : nullptr;
    const __half* pB1_0 = HAS_GI ? Wgi + (0 * HDIM + n0 + r8) * HDIM + c8 * 8 : nullptr;
    const __half* pB1_1 = HAS_GI ? Wgi + (1 * HDIM + n0 + r8) * HDIM + c8 * 8 : nullptr;
    const __half* pB1_2 = HAS_GI ? Wgi + (2 * HDIM + n0 + r8) * HDIM + c8 * 8 : nullptr;

    auto stageB = [&](int ks) {
        const uint32_t bo = (uint32_t)((ks & 1) * BSTRIDE * 2);
        const int ko = ks * 64;
        cp16(sB + bo, pB0_0 + ko);
        cp16(sB + bo + 32 * 72 * 2, pB0_1 + ko);
        cp16(sB + bo + 64 * 72 * 2, pB0_2 + ko);
        if (HAS_GI) {
            const uint32_t bo1 = bo + 160 * 72 * 2;
            cp16(sB + bo1, pB1_0 + ko);
            cp16(sB + bo1 + 32 * 72 * 2, pB1_1 + ko);
            cp16(sB + bo1 + 64 * 72 * 2, pB1_2 + ko);
        }
    };
    auto stageA = [&](int ks) {
        const uint32_t bo = (uint32_t)((ks & 1) * BSTRIDE * 2);
        const int ko = ks * 64;
        cp16(sA + bo, pA0 + ko);
        cp16(sA + bo + 32 * 72 * 2, pA0 + 32 * HDIM + ko);
        if (HAS_GI) {
            const uint32_t bo1 = bo + 160 * 72 * 2;
            cp16(sA + bo1, pA1 + ko);
            cp16(sA + bo1 + 32 * 72 * 2, pA1 + 32 * HDIM + ko);
        }
    };

    float acc_gh[3][2][4];
    float acc_gi[3][2][4];
#pragma unroll
    for (int g = 0; g < 3; g++)
#pragma unroll
        for (int nh = 0; nh < 2; nh++)
#pragma unroll
            for (int i = 0; i < 4; i++) {
                acc_gh[g][nh][i] = 0.f;
                if (HAS_GI) acc_gi[g][nh][i] = 0.f;
            }

    // ldmatrix per-lane addressing (x4 fragment order matches mma A/B).
    const int lane15 = lane & 15;
    const int lhi8   = (lane >> 4) * 8;
    const uint32_t aoff = (uint32_t)(((wm * 16 + lane15) * 72 + lhi8) * 2);
    uint32_t boff[3];
#pragma unroll
    for (int g = 0; g < 3; g++)
        boff[g] = (uint32_t)(((64 + g * 32 + wn * 16 + lane15) * 72 + lhi8) * 2);
    const uint32_t GIOFF = (uint32_t)(160 * 72 * 2);

    // chunk 0: weights before the PDL dependency gate, A tiles after.
    stageB(0); cp_commit();
    if (PDLW) pdl_wait();
    stageA(0); cp_commit();

    for (int ks = 0; ks < 8; ks++) {
        if (ks < 7) { stageA(ks + 1); stageB(ks + 1); cp_commit(); cp_wait<1>(); }
        else        { cp_wait<0>(); }
        __syncthreads();

        const uint32_t base = sbase + (uint32_t)((ks & 1) * BSTRIDE * 2);

#pragma unroll
        for (int kk = 0; kk < 64; kk += 16) {
            uint32_t a0[4], a1[4];
            ldsm4(a0, base + aoff + kk * 2);
            if (HAS_GI) ldsm4(a1, base + GIOFF + aoff + kk * 2);
#pragma unroll
            for (int g = 0; g < 3; g++) {
                uint32_t b[4];
                ldsm4(b, base + boff[g] + kk * 2);
                mma16816(acc_gh[g][0], a0, b[0], b[2]);
                mma16816(acc_gh[g][1], a0, b[1], b[3]);
                if (HAS_GI) {
                    uint32_t c[4];
                    ldsm4(c, base + GIOFF + boff[g] + kk * 2);
                    mma16816(acc_gi[g][0], a1, c[0], c[2]);
                    mma16816(acc_gi[g][1], a1, c[1], c[3]);
                }
            }
        }
        __syncthreads();
    }

    // ---- epilogue: gates fully in registers (known mma C layout) ----
    const int mbase = m0 + wm * 16 + g4;
    const int nbase = n0 + wn * 16 + t4 * 2;

    float fcp[2] = {0.f, 0.f};

#pragma unroll
    for (int hm = 0; hm < 2; hm++) {
        const int row = mbase + hm * 8;
        float xv[IN_FEAT > 0 ? IN_FEAT : 1];
        if constexpr (!HAS_GI) {
            if constexpr (HAS_XFIRST) {
                xv[0] = xfirst[(size_t)row * xfstride];
#pragma unroll
                for (int i = 1; i < IN_FEAT; i++)
                    xv[i] = xrow[row * xstride + i - 1];
            } else {
#pragma unroll
                for (int i = 0; i < IN_FEAT; i++)
                    xv[i] = xrow[row * xstride + i];
            }
        }
#pragma unroll
        for (int nh = 0; nh < 2; nh++) {
            const int j0 = nbase + nh * 8;
            float2 hp = *(const float2*)(hprev + row * HDIM + j0);
            float2 ho;
#pragma unroll
            for (int cc = 0; cc < 2; cc++) {
                const int j = j0 + cc;
                const int ci = hm * 2 + cc;
                float gir, giz, gin;
                if constexpr (HAS_GI) {
                    gir = acc_gi[0][nh][ci] + bih[j];
                    giz = acc_gi[1][nh][ci] + bih[HDIM + j];
                    gin = acc_gi[2][nh][ci] + bih[2 * HDIM + j];
                } else {
                    gir = bih[j];
                    giz = bih[HDIM + j];
                    gin = bih[2 * HDIM + j];
                    const float* wr = WihS + j * IN_FEAT;
                    const float* wz = WihS + (HDIM + j) * IN_FEAT;
                    const float* wn_ = WihS + (2 * HDIM + j) * IN_FEAT;
#pragma unroll
                    for (int i = 0; i < IN_FEAT; i++) {
                        gir += xv[i] * wr[i];
                        giz += xv[i] * wz[i];
                        gin += xv[i] * wn_[i];
                    }
                }
                float ghr = acc_gh[0][nh][ci] + bhh[j];
                float ghz = acc_gh[1][nh][ci] + bhh[HDIM + j];
                float ghn = acc_gh[2][nh][ci] + bhh[2 * HDIM + j];
                float rg = sigmoidf_(gir + ghr);
                float zg = sigmoidf_(giz + ghz);
                float ng = tanhf(gin + rg * ghn);
                float hpv = cc ? hp.y : hp.x;
                float hv = (1.0f - zg) * ng + zg * hpv;
                if (cc) ho.y = hv; else ho.x = hv;
            }
            *(float2*)(hout + row * HDIM + j0) = ho;
            __half2 h2;
            h2.x = __float2half(ho.x);
            h2.y = __float2half(ho.y);
            *(__half2*)(hout16 + row * HDIM + j0) = h2;
            if constexpr (DO_FC)
                fcp[hm] += ho.x * fcW[j0] + ho.y * fcW[j0 + 1];
        }
    }

    if constexpr (DO_FC) {
#pragma unroll
        for (int hm = 0; hm < 2; hm++)
            atomicAdd(outp + (size_t)(mbase + hm * 8) * HORIZON, fcp[hm]);
    }
}

#define ENC_BSTRIDE (320 * 72)
#define DEC_BSTRIDE (160 * 72)
#define ENC_SMEM    (2 * ENC_BSTRIDE * 2)   // 92160 bytes
#define DEC_SMEM    (2 * DEC_BSTRIDE * 2)   // 46080 bytes

// ---------------------------------------------------------------------------
// Fused encoder step: blocks [0,128) -> layer0 h0[t]; [128,256) -> layer1
// h1[t-1] (one-step lag makes the two halves independent).
// ---------------------------------------------------------------------------
__global__ __launch_bounds__(256, 2)
void enc_step_kernel(int t, const float* __restrict__ src,
                     const float* __restrict__ bih0, const float* __restrict__ bhh0,
                     const float* __restrict__ Wih0,
                     const float* __restrict__ bih1, const float* __restrict__ bhh1) {
    extern __shared__ __align__(16) __half dynsmem[];
    const int role = (blockIdx.x < 128) ? 0 : 1;
    const int bid = blockIdx.x & 127;
    const int m0 = (bid >> 4) * 64;
    const int n0 = (bid & 15) * 32;

    if (role == 0) {
        if (t < TSTEPS) {
            const int pw = t & 1, pr = (t + 1) & 1;   // h0[t-1] at parity (t-1)&1
            gru_block<false, 8, false, ENC_BSTRIDE, true, false>(dynsmem, m0, n0,
                g_h0_f16[pr], g_Whh0, nullptr, nullptr,
                bih0, bhh0, Wih0, src + t * 8, TSTEPS * 8, nullptr, 1,
                g_h0_f32[pr], g_h0_f32[pw], g_h0_f16[pw], nullptr, nullptr);
        }
    } else {
        if (t >= 1) {
            const int tt = t - 1;                     // computing h1[tt]
            const int pw = tt & 1, pr = (tt + 1) & 1; // h1[tt-1] parity
            gru_block<true, 0, false, ENC_BSTRIDE, true, false>(dynsmem, m0, n0,
                g_h1_f16[pr], g_Whh1, g_h0_f16[tt & 1], g_Wih1,
                bih1, bhh1, nullptr, nullptr, 0, nullptr, 1,
                g_h1_f32[pr], g_h1_f32[pw], g_h1_f16[pw], nullptr, nullptr);
        }
    }
    pdl_trigger();
}

// ---------------------------------------------------------------------------
// Decoder GRU cell step (gi inline from [last_value, tf_t], 9 features)
// with fused fc head: blocks atomicAdd partial h.fcW into out[:, s]
// (pre-initialized with fc_b). last_value for s>0 is read from out[:, s-1].
// ---------------------------------------------------------------------------
__global__ __launch_bounds__(256, 2)
void dec_step_kernel(int s, const float* __restrict__ tf,
                     const float* __restrict__ cbih, const float* __restrict__ cbhh,
                     const float* __restrict__ cWih,
                     const float* __restrict__ fcW, float* __restrict__ out) {
    extern __shared__ __align__(16) __half dynsmem2[];
    const int bid = blockIdx.x;
    const int m0 = (bid >> 4) * 64;
    const int n0 = (bid & 15) * 32;
    const int pr = s & 1, pw = (s + 1) & 1;
    const float* lastsrc = (s == 0) ? g_lastv : (out + (s - 1));
    const int xfstr = (s == 0) ? 1 : HORIZON;
    gru_block<false, 9, true, DEC_BSTRIDE, true, true>(dynsmem2, m0, n0,
        g_hd_f16[pr], g_cWhh, nullptr, nullptr,
        cbih, cbhh, cWih, tf + s * 8, HORIZON * 8, lastsrc, xfstr,
        g_hd_f32[pr], g_hd_f32[pw], g_hd_f16[pw], fcW, out + s);
    pdl_trigger();
}

// ---------------------------------------------------------------------------
// dec0 linear: hidden0 = h1[T-1] @ dec0_Wᵀ + dec0_b  (one-time, fp32 SIMT)
// ---------------------------------------------------------------------------
__global__ __launch_bounds__(256)
void dec0_kernel(const float* __restrict__ W, const float* __restrict__ bias) {
    pdl_wait();
    __shared__ float As[64][17];
    __shared__ float Ws[64][17];
    const float* A = g_h1_f32[(TSTEPS - 1) & 1];
    const int m0 = blockIdx.y * 64, n0 = blockIdx.x * 64;
    const int tx = threadIdx.x & 15, ty = threadIdx.x >> 4;
    float acc[4][4] = {};
    for (int k0 = 0; k0 < HDIM; k0 += 16) {
#pragma unroll
        for (int i = 0; i < 4; i++) {
            int idx = threadIdx.x + i * 256;
            int r = idx >> 4, c = idx & 15;
            As[r][c] = A[(m0 + r) * HDIM + k0 + c];
            Ws[r][c] = W[(n0 + r) * HDIM + k0 + c];
        }
        __syncthreads();
#pragma unroll
        for (int kk = 0; kk < 16; kk++) {
            float a[4], w[4];
#pragma unroll
            for (int i = 0; i < 4; i++) { a[i] = As[ty * 4 + i][kk]; w[i] = Ws[tx * 4 + i][kk]; }
#pragma unroll
            for (int i = 0; i < 4; i++)
#pragma unroll
                for (int j = 0; j < 4; j++) acc[i][j] += a[i] * w[j];
        }
        __syncthreads();
    }
#pragma unroll
    for (int i = 0; i < 4; i++)
#pragma unroll
        for (int j = 0; j < 4; j++) {
            int m = m0 + ty * 4 + i, n = n0 + tx * 4 + j;
            float v = acc[i][j] + bias[n];
            g_hd_f32[0][m * HDIM + n] = v;
            g_hd_f16[0][m * HDIM + n] = __float2half(v);
        }
    pdl_trigger();
}

// ---------------------------------------------------------------------------
// setup kernels
// ---------------------------------------------------------------------------
__global__ void convert_weights_kernel(const float* __restrict__ Whh0,
                                       const float* __restrict__ Wih1,
                                       const float* __restrict__ Whh1,
                                       const float* __restrict__ cWhh) {
    int i = blockIdx.x * blockDim.x + threadIdx.x;
    if (i < G3H * HDIM) {
        g_Whh0[i] = __float2half(Whh0[i]);
        g_Wih1[i] = __float2half(Wih1[i]);
        g_Whh1[i] = __float2half(Whh1[i]);
        g_cWhh[i] = __float2half(cWhh[i]);
    }
}

__global__ void init_kernel(const float* __restrict__ src,
                            const float* __restrict__ fcb,
                            float* __restrict__ out) {
    int i = blockIdx.x * blockDim.x + threadIdx.x;
    if (i < BATCH * HDIM) {
        g_h0_f32[1][i] = 0.f;
        g_h1_f32[1][i] = 0.f;
        g_h0_f16[1][i] = __float2half(0.f);
        g_h1_f16[1][i] = __float2half(0.f);
    }
    if (i < BATCH) g_lastv[i] = src[i * (TSTEPS * 8) + (TSTEPS - 1) * 8];
    if (i < BATCH * HORIZON) out[i] = fcb[0];   // fc bias pre-load
}

// ---------------------------------------------------------------------------
// PDL launch helper
// ---------------------------------------------------------------------------
static void launch_pdl(const void* func, dim3 grid, dim3 block, size_t smem,
                       void** args) {
    cudaLaunchConfig_t cfg = {};
    cfg.gridDim = grid;
    cfg.blockDim = block;
    cfg.dynamicSmemBytes = smem;
    cfg.stream = 0;
    cudaLaunchAttribute at[1];
    at[0].id = cudaLaunchAttributeProgrammaticStreamSerialization;
    at[0].val.programmaticStreamSerializationAllowed = 1;
    cfg.attrs = at;
    cfg.numAttrs = 1;
    cudaLaunchKernelExC(&cfg, func, args);
}

// ---------------------------------------------------------------------------
extern "C" void kernel_launch(void* const* d_in, const int* in_sizes, int n_in,
                              void* d_out, int out_size) {
    const float* src   = (const float*)d_in[0];
    const float* tf    = (const float*)d_in[1];
    const float* Wih0  = (const float*)d_in[2];
    const float* Whh0  = (const float*)d_in[3];
    const float* bih0  = (const float*)d_in[4];
    const float* bhh0  = (const float*)d_in[5];
    const float* Wih1  = (const float*)d_in[6];
    const float* Whh1  = (const float*)d_in[7];
    const float* bih1  = (const float*)d_in[8];
    const float* bhh1  = (const float*)d_in[9];
    const float* dec0W = (const float*)d_in[10];
    const float* dec0b = (const float*)d_in[11];
    const float* cWih  = (const float*)d_in[12];
    const float* cWhh  = (const float*)d_in[13];
    const float* cbih  = (const float*)d_in[14];
    const float* cbhh  = (const float*)d_in[15];
    const float* fcW   = (const float*)d_in[16];
    const float* fcb   = (const float*)d_in[17];
    float* out = (float*)d_out;

    cudaFuncSetAttribute(enc_step_kernel,
                         cudaFuncAttributeMaxDynamicSharedMemorySize, ENC_SMEM);
    cudaFuncSetAttribute(dec_step_kernel,
                         cudaFuncAttributeMaxDynamicSharedMemorySize, DEC_SMEM);

    convert_weights_kernel<<<(G3H * HDIM + 255) / 256, 256>>>(Whh0, Wih1, Whh1, cWhh);
    init_kernel<<<(BATCH * HDIM + 255) / 256, 256>>>(src, fcb, out);

    // Encoder: T+1 fused launches with PDL chaining
    for (int t = 0; t <= TSTEPS; t++) {
        int tv = t;
        void* args[] = { &tv, (void*)&src, (void*)&bih0, (void*)&bhh0,
                         (void*)&Wih0, (void*)&bih1, (void*)&bhh1 };
        launch_pdl((const void*)enc_step_kernel, dim3(256), dim3(256),
                   ENC_SMEM, args);
    }

    // Decoder init + 48 steps (fc fused into dec_step), all PDL-chained
    {
        void* args[] = { (void*)&dec0W, (void*)&dec0b };
        launch_pdl((const void*)dec0_kernel, dim3(8, 8), dim3(256), 0, args);
    }
    for (int s = 0; s < HORIZON; s++) {
        int sv = s;
        void* args[] = { &sv, (void*)&tf, (void*)&cbih, (void*)&cbhh,
                         (void*)&cWih, (void*)&fcW, (void*)&out };
        launch_pdl((const void*)dec_step_kernel, dim3(128), dim3(256),
                   DEC_SMEM, args);
    }
}